// round 7
// baseline (speedup 1.0000x reference)
#include <cuda_runtime.h>
#include <cuda_bf16.h>
#include <stdint.h>
#include <math.h>

// Problem constants
#define BATCH 2
#define SEQ   2048
#define CDIM  1024
#define NHEAD 16
#define HDIM  64
#define MROWS (BATCH*SEQ)        // 4096
#define N_QKV (3*CDIM)           // 3072

// Scratch (device globals — allocation-free, referenced directly by kernels)
__device__ float g_qkv[(size_t)MROWS * N_QKV];  // [B*T, 3C]
__device__ float g_y[(size_t)MROWS * CDIM];     // [B*T, C]

// ---------------------------------------------------------------------------
// tf32 helpers
// ---------------------------------------------------------------------------
__device__ __forceinline__ uint32_t f2tf32(float x) {
    uint32_t r;
    asm("cvt.rna.tf32.f32 %0, %1;" : "=r"(r) : "f"(x));
    return r;
}

__device__ __forceinline__ void mma_tf32(float* c, const uint32_t* a, const uint32_t* b) {
    asm volatile("mma.sync.aligned.m16n8k8.row.col.f32.tf32.tf32.f32 "
        "{%0,%1,%2,%3}, {%4,%5,%6,%7}, {%8,%9}, {%0,%1,%2,%3};"
        : "+f"(c[0]), "+f"(c[1]), "+f"(c[2]), "+f"(c[3])
        : "r"(a[0]), "r"(a[1]), "r"(a[2]), "r"(a[3]), "r"(b[0]), "r"(b[1]));
}

// ---------------------------------------------------------------------------
// TF32 tensor-core GEMM: C = A[M,K] @ B[K,N], row-major.
// 128x128x32 block tile, 128 threads (4 warps, 2x2), warp tile 64x64
// (MT=4 x NT=8 m16n8k8 fragments) -> 1.0 LDS per MMA (0.125 smem-B/MAC).
// 2 blocks/SM guaranteed by register math. M,N mult of 128, K mult of 32.
// ---------------------------------------------------------------------------
#define TBM 128
#define TBN 128
#define TBK 32
#define A_STRIDE 36    // banks (4*lq + lr): conflict-free A-frag loads
#define B_STRIDE 136   // 136 % 32 == 8 -> banks (8*lr + lq): conflict-free

__device__ __forceinline__ void tgemm_body(
    const float* __restrict__ A, const float* __restrict__ B,
    float* __restrict__ C, int N, int K)
{
    __shared__ uint32_t As[TBM * A_STRIDE];   // tf32 bits, row-major (18.4 KB)
    __shared__ uint32_t Bs[TBK * B_STRIDE];   // tf32 bits, k-major  (17.4 KB)

    const int tid    = threadIdx.x;
    const int lane   = tid & 31;
    const int wid    = tid >> 5;     // 0..3
    const int warp_m = wid & 1;      // 64-row slab
    const int warp_n = wid >> 1;     // 64-col slab
    const int brow   = blockIdx.y * TBM;
    const int bcol   = blockIdx.x * TBN;

    const int lq = lane >> 2;   // 0..7
    const int lr = lane & 3;    // 0..3

    float acc[4][8][4];
    #pragma unroll
    for (int mt = 0; mt < 4; mt++)
        #pragma unroll
        for (int nt = 0; nt < 8; nt++)
            #pragma unroll
            for (int i = 0; i < 4; i++) acc[mt][nt][i] = 0.f;

    for (int k0 = 0; k0 < K; k0 += TBK) {
        // Load A tile: 128 rows x 32 cols = 1024 float4; 8 per thread.
        #pragma unroll
        for (int i = 0; i < 8; i++) {
            int idx = tid + i * 128;
            int r  = idx >> 3;          // 0..127
            int c4 = idx & 7;           // 0..7
            float4 v = *(const float4*)(A + (size_t)(brow + r) * K + k0 + c4 * 4);
            uint4 t;
            t.x = f2tf32(v.x); t.y = f2tf32(v.y);
            t.z = f2tf32(v.z); t.w = f2tf32(v.w);
            *(uint4*)(&As[r * A_STRIDE + c4 * 4]) = t;   // 16B-aligned (144B rows)
        }
        // Load B tile: 32 rows x 128 cols = 1024 float4; 8 per thread.
        #pragma unroll
        for (int i = 0; i < 8; i++) {
            int idx = tid + i * 128;
            int r  = idx >> 5;          // 0..31
            int c4 = idx & 31;          // 0..31
            float4 v = *(const float4*)(B + (size_t)(k0 + r) * N + bcol + c4 * 4);
            uint4 t;
            t.x = f2tf32(v.x); t.y = f2tf32(v.y);
            t.z = f2tf32(v.z); t.w = f2tf32(v.w);
            *(uint4*)(&Bs[r * B_STRIDE + c4 * 4]) = t;
        }
        __syncthreads();

        #pragma unroll
        for (int ks = 0; ks < TBK / 8; ks++) {
            const int kk = ks * 8;
            uint32_t a[4][4], b[8][2];
            #pragma unroll
            for (int mt = 0; mt < 4; mt++) {
                const int r = warp_m * 64 + mt * 16 + lq;
                const int cc = kk + lr;
                a[mt][0] = As[r * A_STRIDE + cc];
                a[mt][1] = As[(r + 8) * A_STRIDE + cc];
                a[mt][2] = As[r * A_STRIDE + cc + 4];
                a[mt][3] = As[(r + 8) * A_STRIDE + cc + 4];
            }
            #pragma unroll
            for (int nt = 0; nt < 8; nt++) {
                const int n = warp_n * 64 + nt * 8 + lq;
                b[nt][0] = Bs[(kk + lr) * B_STRIDE + n];
                b[nt][1] = Bs[(kk + lr + 4) * B_STRIDE + n];
            }
            #pragma unroll
            for (int mt = 0; mt < 4; mt++)
                #pragma unroll
                for (int nt = 0; nt < 8; nt++)
                    mma_tf32(acc[mt][nt], a[mt], b[nt]);
        }
        __syncthreads();
    }

    // Epilogue
    #pragma unroll
    for (int mt = 0; mt < 4; mt++) {
        const int row0 = brow + warp_m * 64 + mt * 16 + lq;
        #pragma unroll
        for (int nt = 0; nt < 8; nt++) {
            const int col = bcol + warp_n * 64 + nt * 8 + 2 * lr;
            *(float2*)(C + (size_t)row0 * N + col) =
                make_float2(acc[mt][nt][0], acc[mt][nt][1]);
            *(float2*)(C + (size_t)(row0 + 8) * N + col) =
                make_float2(acc[mt][nt][2], acc[mt][nt][3]);
        }
    }
}

__global__ __launch_bounds__(128) void qkv_gemm_kernel(
    const float* __restrict__ x, const float* __restrict__ Wqkv)
{
    tgemm_body(x, Wqkv, g_qkv, N_QKV, CDIM);
}

__global__ __launch_bounds__(128) void proj_gemm_kernel(
    const float* __restrict__ Wproj, float* __restrict__ out)
{
    tgemm_body(g_y, Wproj, out, CDIM, CDIM);
}

// ---------------------------------------------------------------------------
// Tensor-core fused causal flash attention (tf32 m16n8k8) — unchanged from R6.
// grid = (SEQ/128, NHEAD, BATCH), 256 threads.
// ---------------------------------------------------------------------------
#define FA_Q 128
#define FA_K 64
#define FA_ST 72

__global__ __launch_bounds__(256) void flash_attn_tc_kernel()
{
    __shared__ uint32_t KVs[2 * FA_K * FA_ST];   // K tile | V tile; Q staging at start
    uint32_t* Ks = KVs;
    uint32_t* Vs = KVs + FA_K * FA_ST;

    const float* __restrict__ qkv = g_qkv;
    float* __restrict__ y = g_y;

    const int tid  = threadIdx.x;
    const int lane = tid & 31;
    const int w    = tid >> 5;
    const int lq   = lane >> 2;
    const int lr   = lane & 3;
    const int h    = blockIdx.y;
    const int b    = blockIdx.z;
    const int q0   = blockIdx.x * FA_Q;
    const size_t rowbase = (size_t)b * SEQ;
    const float scale = 0.125f;

    // Stage Q tile (128 x 64) into KVs, grab A-frags
    #pragma unroll
    for (int i = 0; i < 8; i++) {
        int idx = tid + i * 256;
        int r  = idx >> 4;
        int c4 = idx & 15;
        float4 v = *(const float4*)(qkv + (rowbase + q0 + r) * N_QKV + h * HDIM + c4 * 4);
        uint4 t;
        t.x = f2tf32(v.x); t.y = f2tf32(v.y);
        t.z = f2tf32(v.z); t.w = f2tf32(v.w);
        *(uint4*)&KVs[r * FA_ST + c4 * 4] = t;
    }
    __syncthreads();

    uint32_t qf[8][4];
    {
        const int r0 = (w * 16 + lq) * FA_ST;
        const int r1 = (w * 16 + lq + 8) * FA_ST;
        #pragma unroll
        for (int ks = 0; ks < 8; ks++) {
            const int kk = ks * 8;
            qf[ks][0] = KVs[r0 + kk + lr];
            qf[ks][1] = KVs[r1 + kk + lr];
            qf[ks][2] = KVs[r0 + kk + lr + 4];
            qf[ks][3] = KVs[r1 + kk + lr + 4];
        }
    }

    float o[8][4];
    #pragma unroll
    for (int nt = 0; nt < 8; nt++)
        #pragma unroll
        for (int i = 0; i < 4; i++) o[nt][i] = 0.f;
    float m0 = -INFINITY, m1 = -INFINITY, l0 = 0.f, l1 = 0.f;

    const int row0 = q0 + w * 16 + lq;
    const int row1 = row0 + 8;
    const int wrow_max = q0 + w * 16 + 15;
    const int ntiles = 2 * blockIdx.x + 2;

    for (int t = 0; t < ntiles; t++) {
        const int krow0 = t * FA_K;
        __syncthreads();
        #pragma unroll
        for (int i = 0; i < 4; i++) {
            int idx = tid + i * 256;
            int r  = idx >> 4;
            int c4 = idx & 15;
            const float* base = qkv + (rowbase + krow0 + r) * N_QKV + h * HDIM;
            float4 kv = *(const float4*)(base + CDIM + c4 * 4);
            float4 vv = *(const float4*)(base + 2 * CDIM + c4 * 4);
            uint4 tk, tv;
            tk.x = f2tf32(kv.x); tk.y = f2tf32(kv.y);
            tk.z = f2tf32(kv.z); tk.w = f2tf32(kv.w);
            tv.x = f2tf32(vv.x); tv.y = f2tf32(vv.y);
            tv.z = f2tf32(vv.z); tv.w = f2tf32(vv.w);
            *(uint4*)&Ks[r * FA_ST + c4 * 4] = tk;
            *(uint4*)&Vs[r * FA_ST + c4 * 4] = tv;
        }
        __syncthreads();

        if (krow0 > wrow_max) continue;

        float s[8][4];
        #pragma unroll
        for (int nt = 0; nt < 8; nt++)
            #pragma unroll
            for (int i = 0; i < 4; i++) s[nt][i] = 0.f;

        #pragma unroll
        for (int ks = 0; ks < 8; ks++) {
            const int kk = ks * 8;
            #pragma unroll
            for (int nt = 0; nt < 8; nt++) {
                uint32_t bb[2];
                bb[0] = Ks[(nt * 8 + lq) * FA_ST + kk + lr];
                bb[1] = Ks[(nt * 8 + lq) * FA_ST + kk + lr + 4];
                mma_tf32(s[nt], qf[ks], bb);
            }
        }

        const bool diag = (krow0 + FA_K - 1 > q0 + w * 16);
        #pragma unroll
        for (int nt = 0; nt < 8; nt++) {
            const int col = krow0 + nt * 8 + 2 * lr;
            s[nt][0] = (diag && col     > row0) ? -INFINITY : s[nt][0] * scale;
            s[nt][1] = (diag && col + 1 > row0) ? -INFINITY : s[nt][1] * scale;
            s[nt][2] = (diag && col     > row1) ? -INFINITY : s[nt][2] * scale;
            s[nt][3] = (diag && col + 1 > row1) ? -INFINITY : s[nt][3] * scale;
        }

        float mx0 = -INFINITY, mx1 = -INFINITY;
        #pragma unroll
        for (int nt = 0; nt < 8; nt++) {
            mx0 = fmaxf(mx0, fmaxf(s[nt][0], s[nt][1]));
            mx1 = fmaxf(mx1, fmaxf(s[nt][2], s[nt][3]));
        }
        mx0 = fmaxf(mx0, __shfl_xor_sync(0xffffffffu, mx0, 1));
        mx0 = fmaxf(mx0, __shfl_xor_sync(0xffffffffu, mx0, 2));
        mx1 = fmaxf(mx1, __shfl_xor_sync(0xffffffffu, mx1, 1));
        mx1 = fmaxf(mx1, __shfl_xor_sync(0xffffffffu, mx1, 2));

        const float mn0 = fmaxf(m0, mx0);
        const float mn1 = fmaxf(m1, mx1);
        const float cr0 = __expf(m0 - mn0);
        const float cr1 = __expf(m1 - mn1);
        m0 = mn0; m1 = mn1;

        float sum0 = 0.f, sum1 = 0.f;
        #pragma unroll
        for (int nt = 0; nt < 8; nt++) {
            s[nt][0] = __expf(s[nt][0] - mn0); sum0 += s[nt][0];
            s[nt][1] = __expf(s[nt][1] - mn0); sum0 += s[nt][1];
            s[nt][2] = __expf(s[nt][2] - mn1); sum1 += s[nt][2];
            s[nt][3] = __expf(s[nt][3] - mn1); sum1 += s[nt][3];
        }
        sum0 += __shfl_xor_sync(0xffffffffu, sum0, 1);
        sum0 += __shfl_xor_sync(0xffffffffu, sum0, 2);
        sum1 += __shfl_xor_sync(0xffffffffu, sum1, 1);
        sum1 += __shfl_xor_sync(0xffffffffu, sum1, 2);
        l0 = l0 * cr0 + sum0;
        l1 = l1 * cr1 + sum1;

        #pragma unroll
        for (int nt = 0; nt < 8; nt++) {
            o[nt][0] *= cr0; o[nt][1] *= cr0;
            o[nt][2] *= cr1; o[nt][3] *= cr1;
        }

        const int srcl = (lane & ~3) | (lr >> 1);
        const int srch = srcl + 2;
        const bool odd = (lr & 1);
        #pragma unroll
        for (int kc = 0; kc < 8; kc++) {
            const float c0 = s[kc][0], c1 = s[kc][1];
            const float c2 = s[kc][2], c3 = s[kc][3];
            const float t00 = __shfl_sync(0xffffffffu, c0, srcl);
            const float t01 = __shfl_sync(0xffffffffu, c1, srcl);
            const float t10 = __shfl_sync(0xffffffffu, c2, srcl);
            const float t11 = __shfl_sync(0xffffffffu, c3, srcl);
            const float u00 = __shfl_sync(0xffffffffu, c0, srch);
            const float u01 = __shfl_sync(0xffffffffu, c1, srch);
            const float u10 = __shfl_sync(0xffffffffu, c2, srch);
            const float u11 = __shfl_sync(0xffffffffu, c3, srch);
            uint32_t a[4];
            a[0] = f2tf32(odd ? t01 : t00);
            a[1] = f2tf32(odd ? t11 : t10);
            a[2] = f2tf32(odd ? u01 : u00);
            a[3] = f2tf32(odd ? u11 : u10);
            #pragma unroll
            for (int nt = 0; nt < 8; nt++) {
                uint32_t bb[2];
                bb[0] = Vs[(kc * 8 + lr) * FA_ST + nt * 8 + lq];
                bb[1] = Vs[(kc * 8 + lr + 4) * FA_ST + nt * 8 + lq];
                mma_tf32(o[nt], a, bb);
            }
        }
    }

    const float inv0 = 1.f / l0;
    const float inv1 = 1.f / l1;
    #pragma unroll
    for (int nt = 0; nt < 8; nt++) {
        const int col = h * HDIM + nt * 8 + 2 * lr;
        *(float2*)(y + (rowbase + row0) * CDIM + col) =
            make_float2(o[nt][0] * inv0, o[nt][1] * inv0);
        *(float2*)(y + (rowbase + row1) * CDIM + col) =
            make_float2(o[nt][2] * inv1, o[nt][3] * inv1);
    }
}

// ---------------------------------------------------------------------------
// Launch — pure kernel launches (graph-capture safe).
// ---------------------------------------------------------------------------
extern "C" void kernel_launch(void* const* d_in, const int* in_sizes, int n_in,
                              void* d_out, int out_size)
{
    const float* x     = (const float*)d_in[0];   // [B,T,C]
    const float* Wqkv  = (const float*)d_in[1];   // [C,3C]
    const float* Wproj = (const float*)d_in[2];   // [C,C]
    float* out = (float*)d_out;                   // [B,T,C]

    {   // 1) qkv = x @ Wqkv
        dim3 grid(N_QKV / TBN, MROWS / TBM);
        qkv_gemm_kernel<<<grid, 128>>>(x, Wqkv);
    }
    {   // 2) fused causal attention -> y
        dim3 grid(SEQ / FA_Q, NHEAD, BATCH);
        flash_attn_tc_kernel<<<grid, 256>>>();
    }
    {   // 3) out = y @ Wproj
        dim3 grid(CDIM / TBN, MROWS / TBM);
        proj_gemm_kernel<<<grid, 128>>>(Wproj, out);
    }
}

// round 8
// speedup vs baseline: 1.3308x; 1.3308x over previous
#include <cuda_runtime.h>
#include <cuda_bf16.h>
#include <cuda_fp16.h>
#include <stdint.h>
#include <math.h>

// Problem constants
#define BATCH 2
#define SEQ   2048
#define CDIM  1024
#define NHEAD 16
#define HDIM  64
#define MROWS (BATCH*SEQ)        // 4096
#define N_QKV (3*CDIM)           // 3072

// Scratch (device globals — allocation-free, referenced directly by kernels)
__device__ float g_qkv[(size_t)MROWS * N_QKV];              // [B*T, 3C] (V third unused)
__device__ float g_vt[(size_t)BATCH * NHEAD * HDIM * SEQ];  // V transposed [B,NH,HD,T]
__device__ float g_y[(size_t)MROWS * CDIM];                 // [B*T, C]

// ---------------------------------------------------------------------------
// helpers
// ---------------------------------------------------------------------------
__device__ __forceinline__ uint32_t f2tf32(float x) {
    uint32_t r;
    asm("cvt.rna.tf32.f32 %0, %1;" : "=r"(r) : "f"(x));
    return r;
}

__device__ __forceinline__ uint32_t h2u(float lo, float hi) {
    __half2 h = __floats2half2_rn(lo, hi);
    return *(uint32_t*)&h;
}

__device__ __forceinline__ void mma_tf32(float* c, const uint32_t* a, const uint32_t* b) {
    asm volatile("mma.sync.aligned.m16n8k8.row.col.f32.tf32.tf32.f32 "
        "{%0,%1,%2,%3}, {%4,%5,%6,%7}, {%8,%9}, {%0,%1,%2,%3};"
        : "+f"(c[0]), "+f"(c[1]), "+f"(c[2]), "+f"(c[3])
        : "r"(a[0]), "r"(a[1]), "r"(a[2]), "r"(a[3]), "r"(b[0]), "r"(b[1]));
}

__device__ __forceinline__ void mma_f16(float* c, const uint32_t* a, uint32_t b0, uint32_t b1) {
    asm volatile("mma.sync.aligned.m16n8k16.row.col.f32.f16.f16.f32 "
        "{%0,%1,%2,%3}, {%4,%5,%6,%7}, {%8,%9}, {%0,%1,%2,%3};"
        : "+f"(c[0]), "+f"(c[1]), "+f"(c[2]), "+f"(c[3])
        : "r"(a[0]), "r"(a[1]), "r"(a[2]), "r"(a[3]), "r"(b0), "r"(b1));
}

// ---------------------------------------------------------------------------
// TF32 tensor-core GEMM (R6 config: 256 thr, 8 warps 2x4, warp tile 64x32).
// V_TRANS: blocks with bcol >= 2C write their output transposed into g_vt.
// ---------------------------------------------------------------------------
#define TBM 128
#define TBN 128
#define TBK 32
#define A_STRIDE 36
#define B_STRIDE 132

template <bool V_TRANS>
__device__ __forceinline__ void tgemm_body(
    const float* __restrict__ A, const float* __restrict__ B,
    float* __restrict__ C, int N, int K)
{
    __shared__ uint32_t As[TBM * A_STRIDE];
    __shared__ uint32_t Bs[TBK * B_STRIDE];

    const int tid    = threadIdx.x;
    const int lane   = tid & 31;
    const int wid    = tid >> 5;
    const int warp_m = wid & 1;
    const int warp_n = wid >> 1;
    const int brow   = blockIdx.y * TBM;
    const int bcol   = blockIdx.x * TBN;

    const int lq = lane >> 2;
    const int lr = lane & 3;

    float acc[4][4][4];
    #pragma unroll
    for (int mt = 0; mt < 4; mt++)
        #pragma unroll
        for (int nt = 0; nt < 4; nt++)
            #pragma unroll
            for (int i = 0; i < 4; i++) acc[mt][nt][i] = 0.f;

    for (int k0 = 0; k0 < K; k0 += TBK) {
        #pragma unroll
        for (int i = 0; i < 4; i++) {
            int idx = tid + i * 256;
            int r  = idx >> 3;
            int c4 = idx & 7;
            float4 v = *(const float4*)(A + (size_t)(brow + r) * K + k0 + c4 * 4);
            uint32_t* dst = &As[r * A_STRIDE + c4 * 4];
            dst[0] = f2tf32(v.x); dst[1] = f2tf32(v.y);
            dst[2] = f2tf32(v.z); dst[3] = f2tf32(v.w);
        }
        #pragma unroll
        for (int i = 0; i < 4; i++) {
            int idx = tid + i * 256;
            int r  = idx >> 5;
            int c4 = idx & 31;
            float4 v = *(const float4*)(B + (size_t)(k0 + r) * N + bcol + c4 * 4);
            uint4 t;
            t.x = f2tf32(v.x); t.y = f2tf32(v.y);
            t.z = f2tf32(v.z); t.w = f2tf32(v.w);
            *(uint4*)(&Bs[r * B_STRIDE + c4 * 4]) = t;
        }
        __syncthreads();

        #pragma unroll
        for (int ks = 0; ks < TBK / 8; ks++) {
            const int kk = ks * 8;
            uint32_t a[4][4], b[4][2];
            #pragma unroll
            for (int mt = 0; mt < 4; mt++) {
                const int r = warp_m * 64 + mt * 16 + lq;
                const int cc = kk + lr;
                a[mt][0] = As[r * A_STRIDE + cc];
                a[mt][1] = As[(r + 8) * A_STRIDE + cc];
                a[mt][2] = As[r * A_STRIDE + cc + 4];
                a[mt][3] = As[(r + 8) * A_STRIDE + cc + 4];
            }
            #pragma unroll
            for (int nt = 0; nt < 4; nt++) {
                const int n = warp_n * 32 + nt * 8 + lq;
                b[nt][0] = Bs[(kk + lr) * B_STRIDE + n];
                b[nt][1] = Bs[(kk + lr + 4) * B_STRIDE + n];
            }
            #pragma unroll
            for (int mt = 0; mt < 4; mt++)
                #pragma unroll
                for (int nt = 0; nt < 4; nt++)
                    mma_tf32(acc[mt][nt], a[mt], b[nt]);
        }
        __syncthreads();
    }

    if (V_TRANS && bcol >= 2 * CDIM) {
        // V part: write transposed into g_vt[((b*NH+h)*HD+d)*SEQ + t]
        #pragma unroll
        for (int mt = 0; mt < 4; mt++) {
            const int rowg = brow + warp_m * 64 + mt * 16 + lq;
            const int bb = rowg >> 11;           // / SEQ
            const int t0 = rowg & (SEQ - 1);
            #pragma unroll
            for (int nt = 0; nt < 4; nt++) {
                const int col = (bcol - 2 * CDIM) + warp_n * 32 + nt * 8 + 2 * lr;
                const int h = col >> 6;
                const int d = col & 63;
                float* base = g_vt + ((size_t)(bb * NHEAD + h) * HDIM + d) * SEQ;
                base[t0]           = acc[mt][nt][0];
                base[SEQ + t0]     = acc[mt][nt][1];   // d+1
                base[t0 + 8]       = acc[mt][nt][2];
                base[SEQ + t0 + 8] = acc[mt][nt][3];
            }
        }
    } else {
        #pragma unroll
        for (int mt = 0; mt < 4; mt++) {
            const int row0 = brow + warp_m * 64 + mt * 16 + lq;
            #pragma unroll
            for (int nt = 0; nt < 4; nt++) {
                const int col = bcol + warp_n * 32 + nt * 8 + 2 * lr;
                *(float2*)(C + (size_t)row0 * N + col) =
                    make_float2(acc[mt][nt][0], acc[mt][nt][1]);
                *(float2*)(C + (size_t)(row0 + 8) * N + col) =
                    make_float2(acc[mt][nt][2], acc[mt][nt][3]);
            }
        }
    }
}

__global__ __launch_bounds__(256) void qkv_gemm_kernel(
    const float* __restrict__ x, const float* __restrict__ Wqkv)
{
    tgemm_body<true>(x, Wqkv, g_qkv, N_QKV, CDIM);
}

__global__ __launch_bounds__(256) void proj_gemm_kernel(
    const float* __restrict__ Wproj, float* __restrict__ out)
{
    tgemm_body<false>(g_y, Wproj, out, CDIM, CDIM);
}

// ---------------------------------------------------------------------------
// Tensor-core fused causal flash attention.
// QK^T: tf32 m16n8k8 (unchanged from R6). PV: fp16 m16n8k16 — P C-fragments
// repack directly into f16 A-fragments (no shfl); V^T fp16 in smem, loaded
// from g_vt (written transposed by the QKV GEMM epilogue).
// grid = (SEQ/128, NHEAD, BATCH), 256 threads (8 warps x 16 query rows).
// ---------------------------------------------------------------------------
#define FA_Q 128
#define FA_K 64
#define FA_ST 72     // tf32 K row stride (words); 72 % 32 == 8
#define FA_VST 36    // V^T row stride in half2 units; 36 % 32 == 4

__global__ __launch_bounds__(256) void flash_attn_tc_kernel()
{
    // Union: Q staging (128x72 words) | { K tf32 64x72 , V^T f16 64x36 half2 }
    __shared__ uint32_t KVs[2 * FA_K * FA_ST];          // 36.9 KB
    uint32_t* Ks   = KVs;
    uint32_t* VsTu = KVs + FA_K * FA_ST;                // 64*36 uint32 (half2)

    const float* __restrict__ qkv = g_qkv;
    const float* __restrict__ vt  = g_vt;
    float* __restrict__ y = g_y;

    const int tid  = threadIdx.x;
    const int lane = tid & 31;
    const int w    = tid >> 5;
    const int lq   = lane >> 2;
    const int lr   = lane & 3;
    const int h    = blockIdx.y;
    const int b    = blockIdx.z;
    const int q0   = blockIdx.x * FA_Q;
    const size_t rowbase = (size_t)b * SEQ;
    const float scale = 0.125f;

    // Stage Q tile (128 x 64) into KVs, grab tf32 A-frags
    #pragma unroll
    for (int i = 0; i < 8; i++) {
        int idx = tid + i * 256;
        int r  = idx >> 4;
        int c4 = idx & 15;
        float4 v = *(const float4*)(qkv + (rowbase + q0 + r) * N_QKV + h * HDIM + c4 * 4);
        uint4 t;
        t.x = f2tf32(v.x); t.y = f2tf32(v.y);
        t.z = f2tf32(v.z); t.w = f2tf32(v.w);
        *(uint4*)&KVs[r * FA_ST + c4 * 4] = t;
    }
    __syncthreads();

    uint32_t qf[8][4];
    {
        const int r0 = (w * 16 + lq) * FA_ST;
        const int r1 = (w * 16 + lq + 8) * FA_ST;
        #pragma unroll
        for (int ks = 0; ks < 8; ks++) {
            const int kk = ks * 8;
            qf[ks][0] = KVs[r0 + kk + lr];
            qf[ks][1] = KVs[r1 + kk + lr];
            qf[ks][2] = KVs[r0 + kk + lr + 4];
            qf[ks][3] = KVs[r1 + kk + lr + 4];
        }
    }

    float o[8][4];
    #pragma unroll
    for (int nt = 0; nt < 8; nt++)
        #pragma unroll
        for (int i = 0; i < 4; i++) o[nt][i] = 0.f;
    float m0 = -INFINITY, m1 = -INFINITY, l0 = 0.f, l1 = 0.f;

    const int row0 = q0 + w * 16 + lq;
    const int row1 = row0 + 8;
    const int wrow_max = q0 + w * 16 + 15;
    const int ntiles = 2 * blockIdx.x + 2;

    for (int t = 0; t < ntiles; t++) {
        const int krow0 = t * FA_K;
        __syncthreads();
        // K tile: 64 keys x 64 hd fp32 -> tf32 [key][hd], stride 72
        #pragma unroll
        for (int i = 0; i < 4; i++) {
            int idx = tid + i * 256;
            int r  = idx >> 4;               // key
            int c4 = idx & 15;               // hd group
            const float* base = qkv + (rowbase + krow0 + r) * N_QKV + CDIM + h * HDIM;
            float4 kv = *(const float4*)(base + c4 * 4);
            uint4 tk;
            tk.x = f2tf32(kv.x); tk.y = f2tf32(kv.y);
            tk.z = f2tf32(kv.z); tk.w = f2tf32(kv.w);
            *(uint4*)&Ks[r * FA_ST + c4 * 4] = tk;
        }
        // V^T tile: 64 hd x 64 keys fp32 (from g_vt) -> fp16 half2 [hd][key/2]
        #pragma unroll
        for (int i = 0; i < 4; i++) {
            int idx = tid + i * 256;
            int r  = idx >> 4;               // hd
            int c4 = idx & 15;               // key group of 4
            const float* base = vt + ((size_t)(b * NHEAD + h) * HDIM + r) * SEQ + krow0;
            float4 vv = *(const float4*)(base + c4 * 4);
            VsTu[r * FA_VST + c4 * 2]     = h2u(vv.x, vv.y);
            VsTu[r * FA_VST + c4 * 2 + 1] = h2u(vv.z, vv.w);
        }
        __syncthreads();

        if (krow0 > wrow_max) continue;

        // ---- S = Q K^T (tf32)
        float s[8][4];
        #pragma unroll
        for (int nt = 0; nt < 8; nt++)
            #pragma unroll
            for (int i = 0; i < 4; i++) s[nt][i] = 0.f;

        #pragma unroll
        for (int ks = 0; ks < 8; ks++) {
            const int kk = ks * 8;
            #pragma unroll
            for (int nt = 0; nt < 8; nt++) {
                uint32_t bb[2];
                bb[0] = Ks[(nt * 8 + lq) * FA_ST + kk + lr];
                bb[1] = Ks[(nt * 8 + lq) * FA_ST + kk + lr + 4];
                mma_tf32(s[nt], qf[ks], bb);
            }
        }

        const bool diag = (krow0 + FA_K - 1 > q0 + w * 16);
        #pragma unroll
        for (int nt = 0; nt < 8; nt++) {
            const int col = krow0 + nt * 8 + 2 * lr;
            s[nt][0] = (diag && col     > row0) ? -INFINITY : s[nt][0] * scale;
            s[nt][1] = (diag && col + 1 > row0) ? -INFINITY : s[nt][1] * scale;
            s[nt][2] = (diag && col     > row1) ? -INFINITY : s[nt][2] * scale;
            s[nt][3] = (diag && col + 1 > row1) ? -INFINITY : s[nt][3] * scale;
        }

        // ---- online softmax
        float mx0 = -INFINITY, mx1 = -INFINITY;
        #pragma unroll
        for (int nt = 0; nt < 8; nt++) {
            mx0 = fmaxf(mx0, fmaxf(s[nt][0], s[nt][1]));
            mx1 = fmaxf(mx1, fmaxf(s[nt][2], s[nt][3]));
        }
        mx0 = fmaxf(mx0, __shfl_xor_sync(0xffffffffu, mx0, 1));
        mx0 = fmaxf(mx0, __shfl_xor_sync(0xffffffffu, mx0, 2));
        mx1 = fmaxf(mx1, __shfl_xor_sync(0xffffffffu, mx1, 1));
        mx1 = fmaxf(mx1, __shfl_xor_sync(0xffffffffu, mx1, 2));

        const float mn0 = fmaxf(m0, mx0);
        const float mn1 = fmaxf(m1, mx1);
        const float cr0 = __expf(m0 - mn0);
        const float cr1 = __expf(m1 - mn1);
        m0 = mn0; m1 = mn1;

        float sum0 = 0.f, sum1 = 0.f;
        #pragma unroll
        for (int nt = 0; nt < 8; nt++) {
            s[nt][0] = __expf(s[nt][0] - mn0); sum0 += s[nt][0];
            s[nt][1] = __expf(s[nt][1] - mn0); sum0 += s[nt][1];
            s[nt][2] = __expf(s[nt][2] - mn1); sum1 += s[nt][2];
            s[nt][3] = __expf(s[nt][3] - mn1); sum1 += s[nt][3];
        }
        sum0 += __shfl_xor_sync(0xffffffffu, sum0, 1);
        sum0 += __shfl_xor_sync(0xffffffffu, sum0, 2);
        sum1 += __shfl_xor_sync(0xffffffffu, sum1, 1);
        sum1 += __shfl_xor_sync(0xffffffffu, sum1, 2);
        l0 = l0 * cr0 + sum0;
        l1 = l1 * cr1 + sum1;

        #pragma unroll
        for (int nt = 0; nt < 8; nt++) {
            o[nt][0] *= cr0; o[nt][1] *= cr0;
            o[nt][2] *= cr1; o[nt][3] *= cr1;
        }

        // ---- O += P V (fp16 m16n8k16): P packs straight into A-frags
        #pragma unroll
        for (int ksv = 0; ksv < 4; ksv++) {
            uint32_t a[4];
            a[0] = h2u(s[2*ksv][0],     s[2*ksv][1]);
            a[1] = h2u(s[2*ksv][2],     s[2*ksv][3]);
            a[2] = h2u(s[2*ksv + 1][0], s[2*ksv + 1][1]);
            a[3] = h2u(s[2*ksv + 1][2], s[2*ksv + 1][3]);
            #pragma unroll
            for (int nt = 0; nt < 8; nt++) {
                const int base = (nt * 8 + lq) * FA_VST + 8 * ksv + lr;
                mma_f16(o[nt], a, VsTu[base], VsTu[base + 4]);
            }
        }
    }

    const float inv0 = 1.f / l0;
    const float inv1 = 1.f / l1;
    #pragma unroll
    for (int nt = 0; nt < 8; nt++) {
        const int col = h * HDIM + nt * 8 + 2 * lr;
        *(float2*)(y + (rowbase + row0) * CDIM + col) =
            make_float2(o[nt][0] * inv0, o[nt][1] * inv0);
        *(float2*)(y + (rowbase + row1) * CDIM + col) =
            make_float2(o[nt][2] * inv1, o[nt][3] * inv1);
    }
}

// ---------------------------------------------------------------------------
// Launch — pure kernel launches (graph-capture safe).
// ---------------------------------------------------------------------------
extern "C" void kernel_launch(void* const* d_in, const int* in_sizes, int n_in,
                              void* d_out, int out_size)
{
    const float* x     = (const float*)d_in[0];   // [B,T,C]
    const float* Wqkv  = (const float*)d_in[1];   // [C,3C]
    const float* Wproj = (const float*)d_in[2];   // [C,C]
    float* out = (float*)d_out;                   // [B,T,C]

    {   // 1) qkv = x @ Wqkv (V third written transposed to g_vt)
        dim3 grid(N_QKV / TBN, MROWS / TBM);
        qkv_gemm_kernel<<<grid, 256>>>(x, Wqkv);
    }
    {   // 2) fused causal attention -> y
        dim3 grid(SEQ / FA_Q, NHEAD, BATCH);
        flash_attn_tc_kernel<<<grid, 256>>>();
    }
    {   // 3) out = y @ Wproj
        dim3 grid(CDIM / TBN, MROWS / TBM);
        proj_gemm_kernel<<<grid, 256>>>(Wproj, out);
    }
}